// round 10
// baseline (speedup 1.0000x reference)
#include <cuda_runtime.h>
#include <cuda_bf16.h>
#include <math.h>

#define BB 32
#define TT 512
#define CCH 512
#define HHD 512
#define G4 2048
#define MR (BB*TT)   // 16384

#define UPB 16         // hidden units per persistent block
#define NBLK 64        // persistent grid (32 per direction)
#define DBLK 32        // blocks per direction
#define LTHREADS 512   // threads per recurrence block (16 warps)

// ---- persistent-kernel smem layout (32-bit words) ----
// usH [256 kp][72] (64 cols used), usL same, then hs: 2 planes x 8 slices x [32 kp][40]
#define US_H_OFF 0
#define US_L_OFF 18432
#define HS_OFF   36864
#define LSTM_WORDS 57344
#define LSTM_SMEM (LSTM_WORDS * 4)   // 229376 B

// ---------------- device scratch ----------------
__device__ float d_scale[CCH];
__device__ float d_shift[CCH];
__device__ float d_G[2][(size_t)MR * G4];     // 2 x 134 MB
__device__ unsigned d_xpH[(size_t)MR * 256];  // packed BN(x) hi
__device__ unsigned d_xpL[(size_t)MR * 256];  // packed BN(x) lo
__device__ unsigned d_wpH[2][256 * G4];       // packed W hi per dir
__device__ unsigned d_wpL[2][256 * G4];       // packed W lo per dir
__device__ unsigned d_hpk[2][2][2][256 * 32]; // [dir][pingpong][hi/lo][kp*32+b]
__device__ float d_hout[2][BB * HHD];
__device__ volatile unsigned g_arr[2][DBLK];  // per-block step flags
__device__ volatile unsigned g_done[2];       // leader-published step

// ---------------- bf16 split helpers ----------------
__device__ __forceinline__ void split_bf16(float f, unsigned short &hi, unsigned short &lo) {
    __nv_bfloat16 h = __float2bfloat16(f);
    float hf = __bfloat162float(h);
    __nv_bfloat16 l = __float2bfloat16(f - hf);
    hi = __bfloat16_as_ushort(h);
    lo = __bfloat16_as_ushort(l);
}
__device__ __forceinline__ unsigned pk16(unsigned short a, unsigned short b) {
    return (unsigned)a | ((unsigned)b << 16);
}
__device__ __forceinline__ void mma_bf16(float* d, const unsigned* a, const unsigned* b) {
    asm("mma.sync.aligned.m16n8k16.row.col.f32.bf16.bf16.f32 "
        "{%0,%1,%2,%3}, {%4,%5,%6,%7}, {%8,%9}, {%0,%1,%2,%3};"
        : "+f"(d[0]), "+f"(d[1]), "+f"(d[2]), "+f"(d[3])
        : "r"(a[0]), "r"(a[1]), "r"(a[2]), "r"(a[3]), "r"(b[0]), "r"(b[1]));
}

// ---------------- fast activations ----------------
__device__ __forceinline__ float fsigmoid(float z) {
    return __fdividef(1.f, 1.f + __expf(-z));
}
__device__ __forceinline__ float ftanh(float z) {
    z = fminf(fmaxf(z, -15.f), 15.f);
    float e = __expf(2.f * z);
    return __fdividef(e - 1.f, e + 1.f);
}

// ---------------- BN prep ----------------
__global__ void bn_prep_kernel(const float* __restrict__ gamma,
                               const float* __restrict__ beta,
                               const float* __restrict__ mean,
                               const float* __restrict__ var) {
    int c = threadIdx.x;
    float s = gamma[c] * rsqrtf(var[c] + 1e-3f);
    d_scale[c] = s;
    d_shift[c] = beta[c] - mean[c] * s;
}

// ---------------- pre-split BN(x) into packed bf16 hi/lo planes ----------------
__global__ void split_x_kernel(const float* __restrict__ x) {
    int i = blockIdx.x * blockDim.x + threadIdx.x;
    int row = i >> 8, kp = i & 255;
    float2 v = *(const float2*)(x + (size_t)row * CCH + 2 * kp);
    float2 sc = *(const float2*)(d_scale + 2 * kp);
    float2 sh = *(const float2*)(d_shift + 2 * kp);
    float a = fmaf(v.x, sc.x, sh.x);
    float b = fmaf(v.y, sc.y, sh.y);
    unsigned short he, le, ho, lo;
    split_bf16(a, he, le);
    split_bf16(b, ho, lo);
    d_xpH[i] = pk16(he, ho);
    d_xpL[i] = pk16(le, lo);
}

// ---------------- pre-split W into packed bf16 hi/lo planes ----------------
__global__ void split_w_kernel(const float* __restrict__ Wf,
                               const float* __restrict__ Wb) {
    int i = blockIdx.x * blockDim.x + threadIdx.x;
    int dir = i >> 19;
    int r = i & ((1 << 19) - 1);
    int kp = r >> 11, n = r & 2047;
    const float* W = dir ? Wb : Wf;
    float e = W[(size_t)(2 * kp) * G4 + n];
    float o = W[(size_t)(2 * kp + 1) * G4 + n];
    unsigned short he, le, ho, lo;
    split_bf16(e, he, le);
    split_bf16(o, ho, lo);
    d_wpH[dir][r] = pk16(he, ho);
    d_wpL[dir][r] = pk16(le, lo);
}

// ---------------- big GEMM: G = BN(x)@W + b via 3-split bf16 mma ----------------
#define SSTR2 136

__global__ __launch_bounds__(256, 2) void gemm_tc_kernel(const float* __restrict__ bf,
                                                         const float* __restrict__ bb) {
    __shared__ unsigned AsH[8 * SSTR2], AsL[8 * SSTR2];
    __shared__ unsigned BsH[8 * SSTR2], BsL[8 * SSTR2];

    int dir = blockIdx.z;
    const float* bias = dir ? bb : bf;
    float* Out = d_G[dir];
    const unsigned* wH = d_wpH[dir];
    const unsigned* wL = d_wpL[dir];

    int tid = threadIdx.x;
    int warp = tid >> 5, lane = tid & 31;
    int gid = lane >> 2, tig = lane & 3;
    int wm = warp >> 2, wn = warp & 3;
    int rowBase = blockIdx.y * 128;
    int colBase = blockIdx.x * 128;

    int aRow = tid >> 1;
    int aHalf = tid & 1;
    int bKp = tid >> 5;
    int bN = (tid & 31) * 4;

    const unsigned* xHrow = d_xpH + (size_t)(rowBase + aRow) * 256 + aHalf * 4;
    const unsigned* xLrow = d_xpL + (size_t)(rowBase + aRow) * 256 + aHalf * 4;

    float acc[4][4][4];
    #pragma unroll
    for (int i = 0; i < 4; i++)
        #pragma unroll
        for (int j = 0; j < 4; j++)
            #pragma unroll
            for (int q = 0; q < 4; q++) acc[i][j][q] = 0.f;

    uint4 raH = *(const uint4*)(xHrow);
    uint4 raL = *(const uint4*)(xLrow);
    uint4 rbH = *(const uint4*)(wH + (size_t)bKp * G4 + colBase + bN);
    uint4 rbL = *(const uint4*)(wL + (size_t)bKp * G4 + colBase + bN);

    for (int kt = 0; kt < 32; kt++) {
        {
            int kq = aHalf * 4;
            AsH[(kq + 0) * SSTR2 + aRow] = raH.x;
            AsH[(kq + 1) * SSTR2 + aRow] = raH.y;
            AsH[(kq + 2) * SSTR2 + aRow] = raH.z;
            AsH[(kq + 3) * SSTR2 + aRow] = raH.w;
            AsL[(kq + 0) * SSTR2 + aRow] = raL.x;
            AsL[(kq + 1) * SSTR2 + aRow] = raL.y;
            AsL[(kq + 2) * SSTR2 + aRow] = raL.z;
            AsL[(kq + 3) * SSTR2 + aRow] = raL.w;
            *(uint4*)&BsH[bKp * SSTR2 + bN] = rbH;
            *(uint4*)&BsL[bKp * SSTR2 + bN] = rbL;
        }
        __syncthreads();

        if (kt + 1 < 32) {
            int kp0 = (kt + 1) * 8;
            raH = *(const uint4*)(xHrow + kp0);
            raL = *(const uint4*)(xLrow + kp0);
            rbH = *(const uint4*)(wH + (size_t)(kp0 + bKp) * G4 + colBase + bN);
            rbL = *(const uint4*)(wL + (size_t)(kp0 + bKp) * G4 + colBase + bN);
        }

        {
            unsigned ah[4][4], al[4][4];
            #pragma unroll
            for (int mi = 0; mi < 4; mi++) {
                int m = wm * 64 + mi * 16 + gid;
                int o0 = tig * SSTR2 + m;
                int o1 = (tig + 4) * SSTR2 + m;
                ah[mi][0] = AsH[o0];
                ah[mi][1] = AsH[o0 + 8];
                ah[mi][2] = AsH[o1];
                ah[mi][3] = AsH[o1 + 8];
                al[mi][0] = AsL[o0];
                al[mi][1] = AsL[o0 + 8];
                al[mi][2] = AsL[o1];
                al[mi][3] = AsL[o1 + 8];
            }
            #pragma unroll
            for (int ni = 0; ni < 4; ni++) {
                int n = wn * 32 + ni * 8 + gid;
                unsigned bh[2], bl[2];
                bh[0] = BsH[tig * SSTR2 + n];
                bh[1] = BsH[(tig + 4) * SSTR2 + n];
                bl[0] = BsL[tig * SSTR2 + n];
                bl[1] = BsL[(tig + 4) * SSTR2 + n];
                #pragma unroll
                for (int mi = 0; mi < 4; mi++) {
                    mma_bf16(acc[mi][ni], ah[mi], bh);
                    mma_bf16(acc[mi][ni], ah[mi], bl);
                    mma_bf16(acc[mi][ni], al[mi], bh);
                }
            }
        }
        __syncthreads();
    }

    #pragma unroll
    for (int mi = 0; mi < 4; mi++) {
        int row0 = rowBase + wm * 64 + mi * 16 + gid;
        #pragma unroll
        for (int ni = 0; ni < 4; ni++) {
            int col = colBase + wn * 32 + ni * 8 + tig * 2;
            float b0 = bias[col], b1 = bias[col + 1];
            float2 v0 = make_float2(acc[mi][ni][0] + b0, acc[mi][ni][1] + b1);
            float2 v1 = make_float2(acc[mi][ni][2] + b0, acc[mi][ni][3] + b1);
            *(float2*)(Out + (size_t)row0 * G4 + col) = v0;
            *(float2*)(Out + (size_t)(row0 + 8) * G4 + col) = v1;
        }
    }
}

// ---------------- state init ----------------
__global__ void init_kernel() {
    int i = blockIdx.x * blockDim.x + threadIdx.x;
    unsigned* p = &d_hpk[0][0][0][0];
    int total = 2 * 2 * 2 * 256 * 32;
    for (int j = i; j < total; j += gridDim.x * blockDim.x) p[j] = 0u;
    if (i < 2 * DBLK) ((volatile unsigned*)&g_arr[0][0])[i] = 0u;
    if (i < 2) g_done[i] = 0u;
}

// ---------------- persistent bidirectional LSTM recurrence ----------------
// 64 blocks (32/dir), 512 threads = 16 warps = 2 col-groups x 8 k-slices.
__global__ __launch_bounds__(LTHREADS, 1) void lstm_persist(const float* __restrict__ Uf,
                                                            const float* __restrict__ Ub) {
    extern __shared__ unsigned smem[];
    unsigned* usH = smem + US_H_OFF;     // [256 kp][72] (64 cols)
    unsigned* usL = smem + US_L_OFF;
    unsigned* hsB = smem + HS_OFF;       // plane H: [256 kp][40]; plane L at +10240

    int tid = threadIdx.x;
    int dir = blockIdx.x >> 5;
    int blk = blockIdx.x & 31;
    int u0 = blk * UPB;
    const float* U = dir ? Ub : Uf;
    const float* Gp = d_G[dir];

    // ---- stage + split this block's 64 U columns once ----
    for (int i = tid; i < 256 * 64; i += LTHREADS) {
        int kp = i >> 6, j = i & 63;                    // j = gate*16 + uu
        const float* up = U + (size_t)(2 * kp) * G4 + (j >> 4) * HHD + u0 + (j & 15);
        float e = up[0];
        float o = up[G4];
        unsigned short he, le, ho, lo;
        split_bf16(e, he, le);
        split_bf16(o, ho, lo);
        usH[kp * 72 + j] = pk16(he, ho);
        usL[kp * 72 + j] = pk16(le, lo);
    }

    int w = tid >> 5, lane = tid & 31;
    int gid = lane >> 2, tig = lane & 3;
    int cg = w >> 3;                     // col-group 0/1 (32 cols each)
    int ks = w & 7;                      // k-slice 0..7 (32 kp each)
    int kp0 = ks * 32;
    // staging role: warps 0-7 stage plane H slice w; warps 8-15 plane L slice w-8
    int stP = w >> 3;
    int stS = w & 7;
    // epilogue role: one (batch, unit) per thread
    int eb = tid >> 4, eu = tid & 15;

    float c = 0.f;
    __syncthreads();

    // prefetch gate pre-activations for t=0
    float gzc[4];
    {
        int tt0 = dir ? (TT - 1) : 0;
        const float* gp = Gp + (size_t)(eb * TT + tt0) * G4 + u0 + eu;
        gzc[0] = __ldg(gp);
        gzc[1] = __ldg(gp + 512);
        gzc[2] = __ldg(gp + 1024);
        gzc[3] = __ldg(gp + 1536);
    }

    for (int t = 0; t < TT; t++) {
        int rb = t & 1;
        int nb = rb ^ 1;

        // ---- stage packed h: each warp stages one 32-kp slice of one plane ----
        {
            const uint4* src = (const uint4*)(d_hpk[dir][rb][stP] + stS * 32 * 32);
            unsigned* dst = hsB + stP * 10240;
            int r = lane >> 3;
            int cw = lane & 7;
            #pragma unroll
            for (int i = 0; i < 8; i++) {
                int kpl = i * 4 + r;
                uint4 v = __ldcg(src + kpl * 8 + cw);
                *(uint4*)&dst[(stS * 32 + kpl) * 40 + cw * 4] = v;
            }
        }
        __syncthreads();

        // ---- 3-split bf16 MMA: warp (cg,ks) -> cols cg*32..+31, k-slice ks ----
        float aM[2][4][4], aC[2][4][4];
        #pragma unroll
        for (int i = 0; i < 2; i++)
            #pragma unroll
            for (int j = 0; j < 4; j++)
                #pragma unroll
                for (int q = 0; q < 4; q++) { aM[i][j][q] = 0.f; aC[i][j][q] = 0.f; }

        #pragma unroll
        for (int kt = 0; kt < 4; kt++) {
            int kb = kt * 8;
            unsigned ah[2][4], al[2][4];
            #pragma unroll
            for (int mi = 0; mi < 2; mi++) {
                int m = mi * 16 + gid;
                int o0 = (kp0 + kb + tig) * 40 + m;
                int o1 = (kp0 + kb + tig + 4) * 40 + m;
                ah[mi][0] = hsB[o0];
                ah[mi][1] = hsB[o0 + 8];
                ah[mi][2] = hsB[o1];
                ah[mi][3] = hsB[o1 + 8];
                al[mi][0] = hsB[10240 + o0];
                al[mi][1] = hsB[10240 + o0 + 8];
                al[mi][2] = hsB[10240 + o1];
                al[mi][3] = hsB[10240 + o1 + 8];
            }
            #pragma unroll
            for (int ni = 0; ni < 4; ni++) {
                int n = cg * 32 + ni * 8 + gid;
                int p0 = (kp0 + kb + tig) * 72 + n;
                int p1 = p0 + 4 * 72;
                unsigned bh[2], bl[2];
                bh[0] = usH[p0];
                bh[1] = usH[p1];
                bl[0] = usL[p0];
                bl[1] = usL[p1];
                #pragma unroll
                for (int mi = 0; mi < 2; mi++) {
                    mma_bf16(aM[mi][ni], ah[mi], bh);
                    mma_bf16(aC[mi][ni], ah[mi], bl);
                    mma_bf16(aC[mi][ni], al[mi], bh);
                }
            }
        }

        // all warps must finish reading hs before red overlay
        __syncthreads();

        // ---- combine + write partials: red slice w = hsB + w*1280 floats ----
        {
            float* red = (float*)(hsB + w * 1280);   // [32 lcol][40]
            #pragma unroll
            for (int mi = 0; mi < 2; mi++) {
                int row = mi * 16 + gid;
                #pragma unroll
                for (int ni = 0; ni < 4; ni++) {
                    int lcol = ni * 8 + tig * 2;
                    red[lcol * 40 + row]           = aM[mi][ni][0] + aC[mi][ni][0];
                    red[(lcol + 1) * 40 + row]     = aM[mi][ni][1] + aC[mi][ni][1];
                    red[lcol * 40 + row + 8]       = aM[mi][ni][2] + aC[mi][ni][2];
                    red[(lcol + 1) * 40 + row + 8] = aM[mi][ni][3] + aC[mi][ni][3];
                }
            }
        }

        // prefetch next step's gate pre-activations
        float gzn[4] = {0.f, 0.f, 0.f, 0.f};
        if (t + 1 < TT) {
            int ttn = dir ? (TT - 2 - t) : (t + 1);
            const float* gp = Gp + (size_t)(eb * TT + ttn) * G4 + u0 + eu;
            gzn[0] = __ldg(gp);
            gzn[1] = __ldg(gp + 512);
            gzn[2] = __ldg(gp + 1024);
            gzn[3] = __ldg(gp + 1536);
        }
        __syncthreads();

        // ---- epilogue: reduce 8 k-slices, gates, state update ----
        {
            float z[4];
            #pragma unroll
            for (int g = 0; g < 4; g++) {
                int col = g * 16 + eu;          // 0..63
                int ccg = col >> 5;
                int lcol = col & 31;
                int off = lcol * 40 + eb;
                float s = gzc[g];
                #pragma unroll
                for (int k8 = 0; k8 < 8; k8++)
                    s += ((float*)(hsB + (ccg * 8 + k8) * 1280))[off];
                z[g] = s;
            }
            float ig = fsigmoid(z[0]);
            float fg = fsigmoid(z[1]);
            float gv = ftanh(z[2]);
            float og = fsigmoid(z[3]);
            c = fg * c + ig * gv;
            float hval = og * ftanh(c);

            unsigned short hh, hl;
            split_bf16(hval, hh, hl);
            int gu = u0 + eu;
            int kp = gu >> 1;
            int half = gu & 1;
            ((unsigned short*)d_hpk[dir][nb][0])[(kp * 32 + eb) * 2 + half] = hh;
            ((unsigned short*)d_hpk[dir][nb][1])[(kp * 32 + eb) * 2 + half] = hl;
            if (t == TT - 1) d_hout[dir][eb * HHD + gu] = hval;
        }

        gzc[0] = gzn[0]; gzc[1] = gzn[1]; gzc[2] = gzn[2]; gzc[3] = gzn[3];

        // ---- atomic-free flag-array grid barrier (per direction) ----
        __syncthreads();
        if (tid == 0) {
            __threadfence();
            g_arr[dir][blk] = t + 1;
        }
        if (blk == 0) {
            if (tid < DBLK) {
                while (g_arr[dir][tid] < (unsigned)(t + 1)) { }
            }
            __syncthreads();
            if (tid == 0) {
                __threadfence();
                g_done[dir] = t + 1;
            }
        }
        if (tid == 0) {
            while (g_done[dir] < (unsigned)(t + 1)) { }
            __threadfence();
        }
        __syncthreads();
    }
}

// ---------------- final concat ----------------
__global__ void final_kernel(float* __restrict__ out) {
    int i = blockIdx.x * blockDim.x + threadIdx.x;
    if (i < BB * 2 * HHD) {
        int b = i >> 10;
        int j = i & 1023;
        out[i] = (j < HHD) ? d_hout[0][b * HHD + j]
                           : d_hout[1][b * HHD + j - HHD];
    }
}

// ---------------- launch ----------------
extern "C" void kernel_launch(void* const* d_in, const int* in_sizes, int n_in,
                              void* d_out, int out_size) {
    const float* x     = (const float*)d_in[0];
    const float* gamma = (const float*)d_in[1];
    const float* beta  = (const float*)d_in[2];
    const float* mean  = (const float*)d_in[3];
    const float* var   = (const float*)d_in[4];
    const float* Wf    = (const float*)d_in[5];
    const float* Uf    = (const float*)d_in[6];
    const float* bf    = (const float*)d_in[7];
    const float* Wb    = (const float*)d_in[8];
    const float* Ub    = (const float*)d_in[9];
    const float* bb    = (const float*)d_in[10];
    float* out = (float*)d_out;

    cudaFuncSetAttribute(lstm_persist, cudaFuncAttributeMaxDynamicSharedMemorySize,
                         LSTM_SMEM);

    bn_prep_kernel<<<1, 512>>>(gamma, beta, mean, var);

    split_x_kernel<<<MR * 256 / 256, 256>>>(x);
    split_w_kernel<<<2 * 256 * G4 / 256, 256>>>(Wf, Wb);

    dim3 ggrid(G4 / 128, MR / 128, 2);
    gemm_tc_kernel<<<ggrid, 256>>>(bf, bb);

    init_kernel<<<64, 256>>>();

    lstm_persist<<<NBLK, LTHREADS, LSTM_SMEM>>>(Uf, Ub);

    final_kernel<<<128, 256>>>(out);
}

// round 11
// speedup vs baseline: 1.4249x; 1.4249x over previous
#include <cuda_runtime.h>
#include <cuda_bf16.h>
#include <math.h>

#define BB 32
#define TT 512
#define CCH 512
#define HHD 512
#define G4 2048
#define MR (BB*TT)   // 16384

#define UPB 8          // hidden units per persistent block
#define NBLK 128       // persistent grid (64 per direction)
#define DBLK 64        // blocks per direction

// ---- persistent-kernel smem layout (uint/float words) ----
#define US_H_OFF 0          // [256 kp][40] packed U hi
#define US_L_OFF 10240      // [256 kp][40] packed U lo
#define HS_H_OFF 20480      // 8 warp slices x [32 kp][40] packed h hi (red overlay)
#define HS_L_OFF 30720      // 8 warp slices x [32 kp][40] packed h lo
#define LSTM_WORDS 40960
#define LSTM_SMEM (LSTM_WORDS * 4)   // 163840 B

// ---------------- device scratch ----------------
__device__ float d_scale[CCH];
__device__ float d_shift[CCH];
__device__ float d_G[2][(size_t)MR * G4];     // 2 x 134 MB
__device__ unsigned d_xpH[(size_t)MR * 256];  // packed BN(x) hi
__device__ unsigned d_xpL[(size_t)MR * 256];  // packed BN(x) lo
__device__ unsigned d_wpH[2][256 * G4];       // packed W hi per dir
__device__ unsigned d_wpL[2][256 * G4];       // packed W lo per dir
__device__ unsigned d_hpk[2][2][2][256 * 32]; // [dir][pingpong][hi/lo][kp*32+b]
__device__ float d_hout[2][BB * HHD];
__device__ volatile unsigned g_arr[2][DBLK * 8];  // per-block step flags (32B padded)

// ---------------- bf16 split helpers ----------------
__device__ __forceinline__ void split_bf16(float f, unsigned short &hi, unsigned short &lo) {
    __nv_bfloat16 h = __float2bfloat16(f);
    float hf = __bfloat162float(h);
    __nv_bfloat16 l = __float2bfloat16(f - hf);
    hi = __bfloat16_as_ushort(h);
    lo = __bfloat16_as_ushort(l);
}
__device__ __forceinline__ unsigned pk16(unsigned short a, unsigned short b) {
    return (unsigned)a | ((unsigned)b << 16);
}
__device__ __forceinline__ void mma_bf16(float* d, const unsigned* a, const unsigned* b) {
    asm("mma.sync.aligned.m16n8k16.row.col.f32.bf16.bf16.f32 "
        "{%0,%1,%2,%3}, {%4,%5,%6,%7}, {%8,%9}, {%0,%1,%2,%3};"
        : "+f"(d[0]), "+f"(d[1]), "+f"(d[2]), "+f"(d[3])
        : "r"(a[0]), "r"(a[1]), "r"(a[2]), "r"(a[3]), "r"(b[0]), "r"(b[1]));
}

// ---------------- fast activations ----------------
__device__ __forceinline__ float fsigmoid(float z) {
    return __fdividef(1.f, 1.f + __expf(-z));
}
__device__ __forceinline__ float ftanh(float z) {
    z = fminf(fmaxf(z, -15.f), 15.f);
    float e = __expf(2.f * z);
    return __fdividef(e - 1.f, e + 1.f);
}

// ---------------- BN prep ----------------
__global__ void bn_prep_kernel(const float* __restrict__ gamma,
                               const float* __restrict__ beta,
                               const float* __restrict__ mean,
                               const float* __restrict__ var) {
    int c = threadIdx.x;
    float s = gamma[c] * rsqrtf(var[c] + 1e-3f);
    d_scale[c] = s;
    d_shift[c] = beta[c] - mean[c] * s;
}

// ---------------- pre-split BN(x) into packed bf16 hi/lo planes ----------------
__global__ void split_x_kernel(const float* __restrict__ x) {
    int i = blockIdx.x * blockDim.x + threadIdx.x;
    int row = i >> 8, kp = i & 255;
    float2 v = *(const float2*)(x + (size_t)row * CCH + 2 * kp);
    float2 sc = *(const float2*)(d_scale + 2 * kp);
    float2 sh = *(const float2*)(d_shift + 2 * kp);
    float a = fmaf(v.x, sc.x, sh.x);
    float b = fmaf(v.y, sc.y, sh.y);
    unsigned short he, le, ho, lo;
    split_bf16(a, he, le);
    split_bf16(b, ho, lo);
    d_xpH[i] = pk16(he, ho);
    d_xpL[i] = pk16(le, lo);
}

// ---------------- pre-split W into packed bf16 hi/lo planes ----------------
__global__ void split_w_kernel(const float* __restrict__ Wf,
                               const float* __restrict__ Wb) {
    int i = blockIdx.x * blockDim.x + threadIdx.x;
    int dir = i >> 19;
    int r = i & ((1 << 19) - 1);
    int kp = r >> 11, n = r & 2047;
    const float* W = dir ? Wb : Wf;
    float e = W[(size_t)(2 * kp) * G4 + n];
    float o = W[(size_t)(2 * kp + 1) * G4 + n];
    unsigned short he, le, ho, lo;
    split_bf16(e, he, le);
    split_bf16(o, ho, lo);
    d_wpH[dir][r] = pk16(he, ho);
    d_wpL[dir][r] = pk16(le, lo);
}

// ---------------- big GEMM: G = BN(x)@W + b via 3-split bf16 mma ----------------
// Double-buffered smem tiles: ONE __syncthreads per K-16 tile.
#define SSTR2 136

__global__ __launch_bounds__(256, 2) void gemm_tc_kernel(const float* __restrict__ bf,
                                                         const float* __restrict__ bb) {
    __shared__ unsigned AsH[2][8 * SSTR2], AsL[2][8 * SSTR2];
    __shared__ unsigned BsH[2][8 * SSTR2], BsL[2][8 * SSTR2];

    int dir = blockIdx.z;
    const float* bias = dir ? bb : bf;
    float* Out = d_G[dir];
    const unsigned* wH = d_wpH[dir];
    const unsigned* wL = d_wpL[dir];

    int tid = threadIdx.x;
    int warp = tid >> 5, lane = tid & 31;
    int gid = lane >> 2, tig = lane & 3;
    int wm = warp >> 2, wn = warp & 3;
    int rowBase = blockIdx.y * 128;
    int colBase = blockIdx.x * 128;

    int aRow = tid >> 1;
    int aHalf = tid & 1;
    int bKp = tid >> 5;
    int bN = (tid & 31) * 4;

    const unsigned* xHrow = d_xpH + (size_t)(rowBase + aRow) * 256 + aHalf * 4;
    const unsigned* xLrow = d_xpL + (size_t)(rowBase + aRow) * 256 + aHalf * 4;

    float acc[4][4][4];
    #pragma unroll
    for (int i = 0; i < 4; i++)
        #pragma unroll
        for (int j = 0; j < 4; j++)
            #pragma unroll
            for (int q = 0; q < 4; q++) acc[i][j][q] = 0.f;

    // stage tile 0 into buffer 0
    {
        uint4 raH = *(const uint4*)(xHrow);
        uint4 raL = *(const uint4*)(xLrow);
        uint4 rbH = *(const uint4*)(wH + (size_t)bKp * G4 + colBase + bN);
        uint4 rbL = *(const uint4*)(wL + (size_t)bKp * G4 + colBase + bN);
        int kq = aHalf * 4;
        AsH[0][(kq + 0) * SSTR2 + aRow] = raH.x;
        AsH[0][(kq + 1) * SSTR2 + aRow] = raH.y;
        AsH[0][(kq + 2) * SSTR2 + aRow] = raH.z;
        AsH[0][(kq + 3) * SSTR2 + aRow] = raH.w;
        AsL[0][(kq + 0) * SSTR2 + aRow] = raL.x;
        AsL[0][(kq + 1) * SSTR2 + aRow] = raL.y;
        AsL[0][(kq + 2) * SSTR2 + aRow] = raL.z;
        AsL[0][(kq + 3) * SSTR2 + aRow] = raL.w;
        *(uint4*)&BsH[0][bKp * SSTR2 + bN] = rbH;
        *(uint4*)&BsL[0][bKp * SSTR2 + bN] = rbL;
    }
    __syncthreads();

    for (int kt = 0; kt < 32; kt++) {
        int cur = kt & 1;
        int nxt = cur ^ 1;

        // prefetch next tile into registers (latency overlaps compute)
        uint4 raH, raL, rbH, rbL;
        if (kt + 1 < 32) {
            int kp0 = (kt + 1) * 8;
            raH = *(const uint4*)(xHrow + kp0);
            raL = *(const uint4*)(xLrow + kp0);
            rbH = *(const uint4*)(wH + (size_t)(kp0 + bKp) * G4 + colBase + bN);
            rbL = *(const uint4*)(wL + (size_t)(kp0 + bKp) * G4 + colBase + bN);
        }

        // compute current tile
        {
            unsigned ah[4][4], al[4][4];
            #pragma unroll
            for (int mi = 0; mi < 4; mi++) {
                int m = wm * 64 + mi * 16 + gid;
                int o0 = tig * SSTR2 + m;
                int o1 = (tig + 4) * SSTR2 + m;
                ah[mi][0] = AsH[cur][o0];
                ah[mi][1] = AsH[cur][o0 + 8];
                ah[mi][2] = AsH[cur][o1];
                ah[mi][3] = AsH[cur][o1 + 8];
                al[mi][0] = AsL[cur][o0];
                al[mi][1] = AsL[cur][o0 + 8];
                al[mi][2] = AsL[cur][o1];
                al[mi][3] = AsL[cur][o1 + 8];
            }
            #pragma unroll
            for (int ni = 0; ni < 4; ni++) {
                int n = wn * 32 + ni * 8 + gid;
                unsigned bh[2], bl[2];
                bh[0] = BsH[cur][tig * SSTR2 + n];
                bh[1] = BsH[cur][(tig + 4) * SSTR2 + n];
                bl[0] = BsL[cur][tig * SSTR2 + n];
                bl[1] = BsL[cur][(tig + 4) * SSTR2 + n];
                #pragma unroll
                for (int mi = 0; mi < 4; mi++) {
                    mma_bf16(acc[mi][ni], ah[mi], bh);
                    mma_bf16(acc[mi][ni], ah[mi], bl);
                    mma_bf16(acc[mi][ni], al[mi], bh);
                }
            }
        }

        // store prefetched tile into other buffer, then single sync
        if (kt + 1 < 32) {
            int kq = aHalf * 4;
            AsH[nxt][(kq + 0) * SSTR2 + aRow] = raH.x;
            AsH[nxt][(kq + 1) * SSTR2 + aRow] = raH.y;
            AsH[nxt][(kq + 2) * SSTR2 + aRow] = raH.z;
            AsH[nxt][(kq + 3) * SSTR2 + aRow] = raH.w;
            AsL[nxt][(kq + 0) * SSTR2 + aRow] = raL.x;
            AsL[nxt][(kq + 1) * SSTR2 + aRow] = raL.y;
            AsL[nxt][(kq + 2) * SSTR2 + aRow] = raL.z;
            AsL[nxt][(kq + 3) * SSTR2 + aRow] = raL.w;
            *(uint4*)&BsH[nxt][bKp * SSTR2 + bN] = rbH;
            *(uint4*)&BsL[nxt][bKp * SSTR2 + bN] = rbL;
        }
        __syncthreads();
    }

    #pragma unroll
    for (int mi = 0; mi < 4; mi++) {
        int row0 = rowBase + wm * 64 + mi * 16 + gid;
        #pragma unroll
        for (int ni = 0; ni < 4; ni++) {
            int col = colBase + wn * 32 + ni * 8 + tig * 2;
            float b0 = bias[col], b1 = bias[col + 1];
            float2 v0 = make_float2(acc[mi][ni][0] + b0, acc[mi][ni][1] + b1);
            float2 v1 = make_float2(acc[mi][ni][2] + b0, acc[mi][ni][3] + b1);
            *(float2*)(Out + (size_t)row0 * G4 + col) = v0;
            *(float2*)(Out + (size_t)(row0 + 8) * G4 + col) = v1;
        }
    }
}

// ---------------- state init ----------------
__global__ void init_kernel() {
    int i = blockIdx.x * blockDim.x + threadIdx.x;
    unsigned* p = &d_hpk[0][0][0][0];
    int total = 2 * 2 * 2 * 256 * 32;
    for (int j = i; j < total; j += gridDim.x * blockDim.x) p[j] = 0u;
    if (i < 2 * DBLK * 8) ((volatile unsigned*)&g_arr[0][0])[i] = 0u;
}

// ---------------- persistent bidirectional LSTM recurrence (tensor-core) ----------------
__global__ __launch_bounds__(256, 1) void lstm_persist(const float* __restrict__ Uf,
                                                       const float* __restrict__ Ub) {
    extern __shared__ unsigned smem[];
    unsigned* usH = smem + US_H_OFF;
    unsigned* usL = smem + US_L_OFF;
    unsigned* hsH = smem + HS_H_OFF;
    unsigned* hsL = smem + HS_L_OFF;

    int tid = threadIdx.x;
    int dir = blockIdx.x >> 6;
    int blk = blockIdx.x & 63;
    int u0 = blk * UPB;
    const float* U = dir ? Ub : Uf;
    const float* Gp = d_G[dir];

    for (int i = tid; i < 256 * 32; i += 256) {
        int kp = i >> 5, j = i & 31;
        const float* up = U + (size_t)(2 * kp) * G4 + (j >> 3) * HHD + u0 + (j & 7);
        float e = up[0];
        float o = up[G4];
        unsigned short he, le, ho, lo;
        split_bf16(e, he, le);
        split_bf16(o, ho, lo);
        usH[kp * 40 + j] = pk16(he, ho);
        usL[kp * 40 + j] = pk16(le, lo);
    }

    int w = tid >> 5, lane = tid & 31;
    int gid = lane >> 2, tig = lane & 3;
    int eb = tid >> 3, eu = tid & 7;
    int kp0 = w * 32;

    unsigned* myHsH = hsH + w * 1280;
    unsigned* myHsL = hsL + w * 1280;

    float c = 0.f;
    __syncthreads();

    float gzc[4];
    {
        int tt0 = dir ? (TT - 1) : 0;
        const float* gp = Gp + (size_t)(eb * TT + tt0) * G4 + u0 + eu;
        gzc[0] = __ldg(gp);
        gzc[1] = __ldg(gp + 512);
        gzc[2] = __ldg(gp + 1024);
        gzc[3] = __ldg(gp + 1536);
    }

    for (int t = 0; t < TT; t++) {
        int rb = t & 1;
        int nb = rb ^ 1;

        // ---- stage this warp's packed h slice ----
        {
            const uint4* srcH = (const uint4*)(d_hpk[dir][rb][0] + kp0 * 32);
            const uint4* srcL = (const uint4*)(d_hpk[dir][rb][1] + kp0 * 32);
            int r = lane >> 3;
            int cw = lane & 7;
            #pragma unroll
            for (int i = 0; i < 8; i++) {
                int kpl = i * 4 + r;
                uint4 vh = __ldcg(srcH + kpl * 8 + cw);
                uint4 vl = __ldcg(srcL + kpl * 8 + cw);
                *(uint4*)&myHsH[kpl * 40 + cw * 4] = vh;
                *(uint4*)&myHsL[kpl * 40 + cw * 4] = vl;
            }
        }
        __syncwarp();

        // ---- 3-split bf16 MMA with 2 independent accumulator sets ----
        float aM[2][4][4], aC[2][4][4];
        #pragma unroll
        for (int i = 0; i < 2; i++)
            #pragma unroll
            for (int j = 0; j < 4; j++)
                #pragma unroll
                for (int q = 0; q < 4; q++) { aM[i][j][q] = 0.f; aC[i][j][q] = 0.f; }

        #pragma unroll
        for (int kt = 0; kt < 4; kt++) {
            int kb = kt * 8;
            unsigned ah[2][4], al[2][4];
            #pragma unroll
            for (int mi = 0; mi < 2; mi++) {
                int m = mi * 16 + gid;
                int o0 = (kb + tig) * 40 + m;
                int o1 = (kb + tig + 4) * 40 + m;
                ah[mi][0] = myHsH[o0];
                ah[mi][1] = myHsH[o0 + 8];
                ah[mi][2] = myHsH[o1];
                ah[mi][3] = myHsH[o1 + 8];
                al[mi][0] = myHsL[o0];
                al[mi][1] = myHsL[o0 + 8];
                al[mi][2] = myHsL[o1];
                al[mi][3] = myHsL[o1 + 8];
            }
            #pragma unroll
            for (int ni = 0; ni < 4; ni++) {
                int n = ni * 8 + gid;
                int p0 = (kp0 + kb + tig) * 40 + n;
                int p1 = p0 + 4 * 40;
                unsigned bh[2], bl[2];
                bh[0] = usH[p0];
                bh[1] = usH[p1];
                bl[0] = usL[p0];
                bl[1] = usL[p1];
                #pragma unroll
                for (int mi = 0; mi < 2; mi++) {
                    mma_bf16(aM[mi][ni], ah[mi], bh);
                    mma_bf16(aC[mi][ni], ah[mi], bl);
                    mma_bf16(aC[mi][ni], al[mi], bh);
                }
            }
        }

        // ---- combine + write partials into own hs slice ----
        __syncwarp();
        {
            float* red = (float*)myHsH;
            #pragma unroll
            for (int mi = 0; mi < 2; mi++) {
                int row = mi * 16 + gid;
                #pragma unroll
                for (int ni = 0; ni < 4; ni++) {
                    int col = ni * 8 + tig * 2;
                    red[col * 40 + row]           = aM[mi][ni][0] + aC[mi][ni][0];
                    red[(col + 1) * 40 + row]     = aM[mi][ni][1] + aC[mi][ni][1];
                    red[col * 40 + row + 8]       = aM[mi][ni][2] + aC[mi][ni][2];
                    red[(col + 1) * 40 + row + 8] = aM[mi][ni][3] + aC[mi][ni][3];
                }
            }
        }

        // prefetch next step's gate pre-activations
        float gzn[4] = {0.f, 0.f, 0.f, 0.f};
        if (t + 1 < TT) {
            int ttn = dir ? (TT - 2 - t) : (t + 1);
            const float* gp = Gp + (size_t)(eb * TT + ttn) * G4 + u0 + eu;
            gzn[0] = __ldg(gp);
            gzn[1] = __ldg(gp + 512);
            gzn[2] = __ldg(gp + 1024);
            gzn[3] = __ldg(gp + 1536);
        }
        __syncthreads();

        // ---- epilogue ----
        {
            float z[4];
            #pragma unroll
            for (int g = 0; g < 4; g++) {
                int off = (g * 8 + eu) * 40 + eb;
                float s = gzc[g];
                #pragma unroll
                for (int w8 = 0; w8 < 8; w8++)
                    s += ((float*)(hsH + w8 * 1280))[off];
                z[g] = s;
            }
            float ig = fsigmoid(z[0]);
            float fg = fsigmoid(z[1]);
            float gv = ftanh(z[2]);
            float og = fsigmoid(z[3]);
            c = fg * c + ig * gv;
            float hval = og * ftanh(c);

            unsigned short hh, hl;
            split_bf16(hval, hh, hl);
            int gu = u0 + eu;
            int kp = gu >> 1;
            int half = gu & 1;
            ((unsigned short*)d_hpk[dir][nb][0])[(kp * 32 + eb) * 2 + half] = hh;
            ((unsigned short*)d_hpk[dir][nb][1])[(kp * 32 + eb) * 2 + half] = hl;
            if (t == TT - 1) d_hout[dir][eb * HHD + gu] = hval;
        }

        gzc[0] = gzn[0]; gzc[1] = gzn[1]; gzc[2] = gzn[2]; gzc[3] = gzn[3];

        // ---- flat all-poll grid barrier (per direction, no leader hop) ----
        __syncthreads();
        if (tid == 0) {
            __threadfence();
            g_arr[dir][blk * 8] = t + 1;
        }
        if (tid < DBLK) {
            while (g_arr[dir][tid * 8] < (unsigned)(t + 1)) { }
        }
        __syncthreads();
    }
}

// ---------------- final concat ----------------
__global__ void final_kernel(float* __restrict__ out) {
    int i = blockIdx.x * blockDim.x + threadIdx.x;
    if (i < BB * 2 * HHD) {
        int b = i >> 10;
        int j = i & 1023;
        out[i] = (j < HHD) ? d_hout[0][b * HHD + j]
                           : d_hout[1][b * HHD + j - HHD];
    }
}

// ---------------- launch ----------------
extern "C" void kernel_launch(void* const* d_in, const int* in_sizes, int n_in,
                              void* d_out, int out_size) {
    const float* x     = (const float*)d_in[0];
    const float* gamma = (const float*)d_in[1];
    const float* beta  = (const float*)d_in[2];
    const float* mean  = (const float*)d_in[3];
    const float* var   = (const float*)d_in[4];
    const float* Wf    = (const float*)d_in[5];
    const float* Uf    = (const float*)d_in[6];
    const float* bf    = (const float*)d_in[7];
    const float* Wb    = (const float*)d_in[8];
    const float* Ub    = (const float*)d_in[9];
    const float* bb    = (const float*)d_in[10];
    float* out = (float*)d_out;

    cudaFuncSetAttribute(lstm_persist, cudaFuncAttributeMaxDynamicSharedMemorySize,
                         LSTM_SMEM);

    bn_prep_kernel<<<1, 512>>>(gamma, beta, mean, var);

    split_x_kernel<<<MR * 256 / 256, 256>>>(x);
    split_w_kernel<<<2 * 256 * G4 / 256, 256>>>(Wf, Wb);

    dim3 ggrid(G4 / 128, MR / 128, 2);
    gemm_tc_kernel<<<ggrid, 256>>>(bf, bb);

    init_kernel<<<64, 256>>>();

    lstm_persist<<<NBLK, 256, LSTM_SMEM>>>(Uf, Ub);

    final_kernel<<<128, 256>>>(out);
}

// round 13
// speedup vs baseline: 1.4285x; 1.0025x over previous
#include <cuda_runtime.h>
#include <cuda_bf16.h>
#include <math.h>

#define BB 32
#define TT 512
#define CCH 512
#define HHD 512
#define G4 2048
#define MR (BB*TT)   // 16384

#define UPB 8          // hidden units per persistent block
#define NBLK 128       // persistent grid (64 per direction)
#define DBLK 64        // blocks per direction

// ---- persistent-kernel smem layout (uint/float words) ----
#define US_H_OFF 0          // [256 kp][40] packed U hi
#define US_L_OFF 10240      // [256 kp][40] packed U lo
#define HS_H_OFF 20480      // 8 warp slices x [32 kp][40] packed h hi (red overlay)
#define HS_L_OFF 30720      // 8 warp slices x [32 kp][40] packed h lo
#define LSTM_WORDS 40960
#define LSTM_SMEM (LSTM_WORDS * 4)   // 163840 B

// ---------------- device scratch ----------------
__device__ float d_scale[CCH];
__device__ float d_shift[CCH];
__device__ float d_G[2][(size_t)MR * G4];     // 2 x 134 MB
__device__ unsigned d_xpH[(size_t)MR * 256];  // packed BN(x) hi
__device__ unsigned d_xpL[(size_t)MR * 256];  // packed BN(x) lo
__device__ unsigned d_wpH[2][256 * G4];       // packed W hi per dir
__device__ unsigned d_wpL[2][256 * G4];       // packed W lo per dir
__device__ unsigned d_hpk[2][2][2][256 * 32]; // [dir][pingpong][hi/lo][kp*32+b]
__device__ float d_hout[2][BB * HHD];
__device__ volatile unsigned g_arr[2][DBLK];  // per-block step flags
__device__ volatile unsigned g_done[2];       // leader-published step

// ---------------- bf16 split helpers ----------------
__device__ __forceinline__ void split_bf16(float f, unsigned short &hi, unsigned short &lo) {
    __nv_bfloat16 h = __float2bfloat16(f);
    float hf = __bfloat162float(h);
    __nv_bfloat16 l = __float2bfloat16(f - hf);
    hi = __bfloat16_as_ushort(h);
    lo = __bfloat16_as_ushort(l);
}
__device__ __forceinline__ unsigned pk16(unsigned short a, unsigned short b) {
    return (unsigned)a | ((unsigned)b << 16);
}
__device__ __forceinline__ void mma_bf16(float* d, const unsigned* a, const unsigned* b) {
    asm("mma.sync.aligned.m16n8k16.row.col.f32.bf16.bf16.f32 "
        "{%0,%1,%2,%3}, {%4,%5,%6,%7}, {%8,%9}, {%0,%1,%2,%3};"
        : "+f"(d[0]), "+f"(d[1]), "+f"(d[2]), "+f"(d[3])
        : "r"(a[0]), "r"(a[1]), "r"(a[2]), "r"(a[3]), "r"(b[0]), "r"(b[1]));
}

// ---------------- fast activations ----------------
__device__ __forceinline__ float fsigmoid(float z) {
    return __fdividef(1.f, 1.f + __expf(-z));
}
__device__ __forceinline__ float ftanh(float z) {
    z = fminf(fmaxf(z, -15.f), 15.f);
    float e = __expf(2.f * z);
    return __fdividef(e - 1.f, e + 1.f);
}

// ---------------- BN prep ----------------
__global__ void bn_prep_kernel(const float* __restrict__ gamma,
                               const float* __restrict__ beta,
                               const float* __restrict__ mean,
                               const float* __restrict__ var) {
    int c = threadIdx.x;
    float s = gamma[c] * rsqrtf(var[c] + 1e-3f);
    d_scale[c] = s;
    d_shift[c] = beta[c] - mean[c] * s;
}

// ---------------- pre-split BN(x) into packed bf16 hi/lo planes ----------------
__global__ void split_x_kernel(const float* __restrict__ x) {
    int i = blockIdx.x * blockDim.x + threadIdx.x;
    int row = i >> 8, kp = i & 255;
    float2 v = *(const float2*)(x + (size_t)row * CCH + 2 * kp);
    float2 sc = *(const float2*)(d_scale + 2 * kp);
    float2 sh = *(const float2*)(d_shift + 2 * kp);
    float a = fmaf(v.x, sc.x, sh.x);
    float b = fmaf(v.y, sc.y, sh.y);
    unsigned short he, le, ho, lo;
    split_bf16(a, he, le);
    split_bf16(b, ho, lo);
    d_xpH[i] = pk16(he, ho);
    d_xpL[i] = pk16(le, lo);
}

// ---------------- pre-split W into packed bf16 hi/lo planes ----------------
__global__ void split_w_kernel(const float* __restrict__ Wf,
                               const float* __restrict__ Wb) {
    int i = blockIdx.x * blockDim.x + threadIdx.x;
    int dir = i >> 19;
    int r = i & ((1 << 19) - 1);
    int kp = r >> 11, n = r & 2047;
    const float* W = dir ? Wb : Wf;
    float e = W[(size_t)(2 * kp) * G4 + n];
    float o = W[(size_t)(2 * kp + 1) * G4 + n];
    unsigned short he, le, ho, lo;
    split_bf16(e, he, le);
    split_bf16(o, ho, lo);
    d_wpH[dir][r] = pk16(he, ho);
    d_wpL[dir][r] = pk16(le, lo);
}

// ---------------- big GEMM: G = BN(x)@W + b via 3-split bf16 mma ----------------
// Double-buffered smem tiles: ONE __syncthreads per K-16 tile.
#define SSTR2 136

__global__ __launch_bounds__(256, 2) void gemm_tc_kernel(const float* __restrict__ bf,
                                                         const float* __restrict__ bb) {
    __shared__ unsigned AsH[2][8 * SSTR2], AsL[2][8 * SSTR2];
    __shared__ unsigned BsH[2][8 * SSTR2], BsL[2][8 * SSTR2];

    int dir = blockIdx.z;
    const float* bias = dir ? bb : bf;
    float* Out = d_G[dir];
    const unsigned* wH = d_wpH[dir];
    const unsigned* wL = d_wpL[dir];

    int tid = threadIdx.x;
    int warp = tid >> 5, lane = tid & 31;
    int gid = lane >> 2, tig = lane & 3;
    int wm = warp >> 2, wn = warp & 3;
    int rowBase = blockIdx.y * 128;
    int colBase = blockIdx.x * 128;

    int aRow = tid >> 1;
    int aHalf = tid & 1;
    int bKp = tid >> 5;
    int bN = (tid & 31) * 4;

    const unsigned* xHrow = d_xpH + (size_t)(rowBase + aRow) * 256 + aHalf * 4;
    const unsigned* xLrow = d_xpL + (size_t)(rowBase + aRow) * 256 + aHalf * 4;

    float acc[4][4][4];
    #pragma unroll
    for (int i = 0; i < 4; i++)
        #pragma unroll
        for (int j = 0; j < 4; j++)
            #pragma unroll
            for (int q = 0; q < 4; q++) acc[i][j][q] = 0.f;

    // stage tile 0 into buffer 0
    {
        uint4 raH = *(const uint4*)(xHrow);
        uint4 raL = *(const uint4*)(xLrow);
        uint4 rbH = *(const uint4*)(wH + (size_t)bKp * G4 + colBase + bN);
        uint4 rbL = *(const uint4*)(wL + (size_t)bKp * G4 + colBase + bN);
        int kq = aHalf * 4;
        AsH[0][(kq + 0) * SSTR2 + aRow] = raH.x;
        AsH[0][(kq + 1) * SSTR2 + aRow] = raH.y;
        AsH[0][(kq + 2) * SSTR2 + aRow] = raH.z;
        AsH[0][(kq + 3) * SSTR2 + aRow] = raH.w;
        AsL[0][(kq + 0) * SSTR2 + aRow] = raL.x;
        AsL[0][(kq + 1) * SSTR2 + aRow] = raL.y;
        AsL[0][(kq + 2) * SSTR2 + aRow] = raL.z;
        AsL[0][(kq + 3) * SSTR2 + aRow] = raL.w;
        *(uint4*)&BsH[0][bKp * SSTR2 + bN] = rbH;
        *(uint4*)&BsL[0][bKp * SSTR2 + bN] = rbL;
    }
    __syncthreads();

    for (int kt = 0; kt < 32; kt++) {
        int cur = kt & 1;
        int nxt = cur ^ 1;

        uint4 raH, raL, rbH, rbL;
        if (kt + 1 < 32) {
            int kp0 = (kt + 1) * 8;
            raH = *(const uint4*)(xHrow + kp0);
            raL = *(const uint4*)(xLrow + kp0);
            rbH = *(const uint4*)(wH + (size_t)(kp0 + bKp) * G4 + colBase + bN);
            rbL = *(const uint4*)(wL + (size_t)(kp0 + bKp) * G4 + colBase + bN);
        }

        {
            unsigned ah[4][4], al[4][4];
            #pragma unroll
            for (int mi = 0; mi < 4; mi++) {
                int m = wm * 64 + mi * 16 + gid;
                int o0 = tig * SSTR2 + m;
                int o1 = (tig + 4) * SSTR2 + m;
                ah[mi][0] = AsH[cur][o0];
                ah[mi][1] = AsH[cur][o0 + 8];
                ah[mi][2] = AsH[cur][o1];
                ah[mi][3] = AsH[cur][o1 + 8];
                al[mi][0] = AsL[cur][o0];
                al[mi][1] = AsL[cur][o0 + 8];
                al[mi][2] = AsL[cur][o1];
                al[mi][3] = AsL[cur][o1 + 8];
            }
            #pragma unroll
            for (int ni = 0; ni < 4; ni++) {
                int n = wn * 32 + ni * 8 + gid;
                unsigned bh[2], bl[2];
                bh[0] = BsH[cur][tig * SSTR2 + n];
                bh[1] = BsH[cur][(tig + 4) * SSTR2 + n];
                bl[0] = BsL[cur][tig * SSTR2 + n];
                bl[1] = BsL[cur][(tig + 4) * SSTR2 + n];
                #pragma unroll
                for (int mi = 0; mi < 4; mi++) {
                    mma_bf16(acc[mi][ni], ah[mi], bh);
                    mma_bf16(acc[mi][ni], ah[mi], bl);
                    mma_bf16(acc[mi][ni], al[mi], bh);
                }
            }
        }

        if (kt + 1 < 32) {
            int kq = aHalf * 4;
            AsH[nxt][(kq + 0) * SSTR2 + aRow] = raH.x;
            AsH[nxt][(kq + 1) * SSTR2 + aRow] = raH.y;
            AsH[nxt][(kq + 2) * SSTR2 + aRow] = raH.z;
            AsH[nxt][(kq + 3) * SSTR2 + aRow] = raH.w;
            AsL[nxt][(kq + 0) * SSTR2 + aRow] = raL.x;
            AsL[nxt][(kq + 1) * SSTR2 + aRow] = raL.y;
            AsL[nxt][(kq + 2) * SSTR2 + aRow] = raL.z;
            AsL[nxt][(kq + 3) * SSTR2 + aRow] = raL.w;
            *(uint4*)&BsH[nxt][bKp * SSTR2 + bN] = rbH;
            *(uint4*)&BsL[nxt][bKp * SSTR2 + bN] = rbL;
        }
        __syncthreads();
    }

    #pragma unroll
    for (int mi = 0; mi < 4; mi++) {
        int row0 = rowBase + wm * 64 + mi * 16 + gid;
        #pragma unroll
        for (int ni = 0; ni < 4; ni++) {
            int col = colBase + wn * 32 + ni * 8 + tig * 2;
            float b0 = bias[col], b1 = bias[col + 1];
            float2 v0 = make_float2(acc[mi][ni][0] + b0, acc[mi][ni][1] + b1);
            float2 v1 = make_float2(acc[mi][ni][2] + b0, acc[mi][ni][3] + b1);
            *(float2*)(Out + (size_t)row0 * G4 + col) = v0;
            *(float2*)(Out + (size_t)(row0 + 8) * G4 + col) = v1;
        }
    }
}

// ---------------- state init ----------------
__global__ void init_kernel() {
    int i = blockIdx.x * blockDim.x + threadIdx.x;
    unsigned* p = &d_hpk[0][0][0][0];
    int total = 2 * 2 * 2 * 256 * 32;
    for (int j = i; j < total; j += gridDim.x * blockDim.x) p[j] = 0u;
    if (i < 2 * DBLK) ((volatile unsigned*)&g_arr[0][0])[i] = 0u;
    if (i < 2) g_done[i] = 0u;
}

// ---------------- persistent bidirectional LSTM recurrence (tensor-core) ----------------
__global__ __launch_bounds__(256, 1) void lstm_persist(const float* __restrict__ Uf,
                                                       const float* __restrict__ Ub) {
    extern __shared__ unsigned smem[];
    unsigned* usH = smem + US_H_OFF;
    unsigned* usL = smem + US_L_OFF;
    unsigned* hsH = smem + HS_H_OFF;
    unsigned* hsL = smem + HS_L_OFF;

    int tid = threadIdx.x;
    int dir = blockIdx.x >> 6;
    int blk = blockIdx.x & 63;
    int u0 = blk * UPB;
    const float* U = dir ? Ub : Uf;
    const float* Gp = d_G[dir];

    for (int i = tid; i < 256 * 32; i += 256) {
        int kp = i >> 5, j = i & 31;
        const float* up = U + (size_t)(2 * kp) * G4 + (j >> 3) * HHD + u0 + (j & 7);
        float e = up[0];
        float o = up[G4];
        unsigned short he, le, ho, lo;
        split_bf16(e, he, le);
        split_bf16(o, ho, lo);
        usH[kp * 40 + j] = pk16(he, ho);
        usL[kp * 40 + j] = pk16(le, lo);
    }

    int w = tid >> 5, lane = tid & 31;
    int gid = lane >> 2, tig = lane & 3;
    int eb = tid >> 3, eu = tid & 7;
    int kp0 = w * 32;

    unsigned* myHsH = hsH + w * 1280;
    unsigned* myHsL = hsL + w * 1280;

    float c = 0.f;
    __syncthreads();

    float gzc[4];
    {
        int tt0 = dir ? (TT - 1) : 0;
        const float* gp = Gp + (size_t)(eb * TT + tt0) * G4 + u0 + eu;
        gzc[0] = __ldg(gp);
        gzc[1] = __ldg(gp + 512);
        gzc[2] = __ldg(gp + 1024);
        gzc[3] = __ldg(gp + 1536);
    }

    for (int t = 0; t < TT; t++) {
        int rb = t & 1;
        int nb = rb ^ 1;

        // ---- stage this warp's packed h slice ----
        {
            const uint4* srcH = (const uint4*)(d_hpk[dir][rb][0] + kp0 * 32);
            const uint4* srcL = (const uint4*)(d_hpk[dir][rb][1] + kp0 * 32);
            int r = lane >> 3;
            int cw = lane & 7;
            #pragma unroll
            for (int i = 0; i < 8; i++) {
                int kpl = i * 4 + r;
                uint4 vh = __ldcg(srcH + kpl * 8 + cw);
                uint4 vl = __ldcg(srcL + kpl * 8 + cw);
                *(uint4*)&myHsH[kpl * 40 + cw * 4] = vh;
                *(uint4*)&myHsL[kpl * 40 + cw * 4] = vl;
            }
        }
        __syncwarp();

        // ---- 3-split bf16 MMA with 2 independent accumulator sets ----
        float aM[2][4][4], aC[2][4][4];
        #pragma unroll
        for (int i = 0; i < 2; i++)
            #pragma unroll
            for (int j = 0; j < 4; j++)
                #pragma unroll
                for (int q = 0; q < 4; q++) { aM[i][j][q] = 0.f; aC[i][j][q] = 0.f; }

        #pragma unroll
        for (int kt = 0; kt < 4; kt++) {
            int kb = kt * 8;
            unsigned ah[2][4], al[2][4];
            #pragma unroll
            for (int mi = 0; mi < 2; mi++) {
                int m = mi * 16 + gid;
                int o0 = (kb + tig) * 40 + m;
                int o1 = (kb + tig + 4) * 40 + m;
                ah[mi][0] = myHsH[o0];
                ah[mi][1] = myHsH[o0 + 8];
                ah[mi][2] = myHsH[o1];
                ah[mi][3] = myHsH[o1 + 8];
                al[mi][0] = myHsL[o0];
                al[mi][1] = myHsL[o0 + 8];
                al[mi][2] = myHsL[o1];
                al[mi][3] = myHsL[o1 + 8];
            }
            #pragma unroll
            for (int ni = 0; ni < 4; ni++) {
                int n = ni * 8 + gid;
                int p0 = (kp0 + kb + tig) * 40 + n;
                int p1 = p0 + 4 * 40;
                unsigned bh[2], bl[2];
                bh[0] = usH[p0];
                bh[1] = usH[p1];
                bl[0] = usL[p0];
                bl[1] = usL[p1];
                #pragma unroll
                for (int mi = 0; mi < 2; mi++) {
                    mma_bf16(aM[mi][ni], ah[mi], bh);
                    mma_bf16(aC[mi][ni], ah[mi], bl);
                    mma_bf16(aC[mi][ni], al[mi], bh);
                }
            }
        }

        // ---- combine + write partials into own hs slice ----
        __syncwarp();
        {
            float* red = (float*)myHsH;
            #pragma unroll
            for (int mi = 0; mi < 2; mi++) {
                int row = mi * 16 + gid;
                #pragma unroll
                for (int ni = 0; ni < 4; ni++) {
                    int col = ni * 8 + tig * 2;
                    red[col * 40 + row]           = aM[mi][ni][0] + aC[mi][ni][0];
                    red[(col + 1) * 40 + row]     = aM[mi][ni][1] + aC[mi][ni][1];
                    red[col * 40 + row + 8]       = aM[mi][ni][2] + aC[mi][ni][2];
                    red[(col + 1) * 40 + row + 8] = aM[mi][ni][3] + aC[mi][ni][3];
                }
            }
        }

        // prefetch next step's gate pre-activations
        float gzn[4] = {0.f, 0.f, 0.f, 0.f};
        if (t + 1 < TT) {
            int ttn = dir ? (TT - 2 - t) : (t + 1);
            const float* gp = Gp + (size_t)(eb * TT + ttn) * G4 + u0 + eu;
            gzn[0] = __ldg(gp);
            gzn[1] = __ldg(gp + 512);
            gzn[2] = __ldg(gp + 1024);
            gzn[3] = __ldg(gp + 1536);
        }
        __syncthreads();

        // ---- epilogue ----
        {
            float z[4];
            #pragma unroll
            for (int g = 0; g < 4; g++) {
                int off = (g * 8 + eu) * 40 + eb;
                float s = gzc[g];
                #pragma unroll
                for (int w8 = 0; w8 < 8; w8++)
                    s += ((float*)(hsH + w8 * 1280))[off];
                z[g] = s;
            }
            float ig = fsigmoid(z[0]);
            float fg = fsigmoid(z[1]);
            float gv = ftanh(z[2]);
            float og = fsigmoid(z[3]);
            c = fg * c + ig * gv;
            float hval = og * ftanh(c);

            unsigned short hh, hl;
            split_bf16(hval, hh, hl);
            int gu = u0 + eu;
            int kp = gu >> 1;
            int half = gu & 1;
            ((unsigned short*)d_hpk[dir][nb][0])[(kp * 32 + eb) * 2 + half] = hh;
            ((unsigned short*)d_hpk[dir][nb][1])[(kp * 32 + eb) * 2 + half] = hl;
            if (t == TT - 1) d_hout[dir][eb * HHD + gu] = hval;
        }

        gzc[0] = gzn[0]; gzc[1] = gzn[1]; gzc[2] = gzn[2]; gzc[3] = gzn[3];

        // ---- leader/publish grid barrier (per direction) ----
        __syncthreads();
        if (tid == 0) {
            __threadfence();
            g_arr[dir][blk] = t + 1;
        }
        if (blk == 0) {
            if (tid < DBLK) {
                while (g_arr[dir][tid] < (unsigned)(t + 1)) { }
            }
            __syncthreads();
            if (tid == 0) {
                __threadfence();
                g_done[dir] = t + 1;
            }
        }
        if (tid == 0) {
            while (g_done[dir] < (unsigned)(t + 1)) { }
            __threadfence();
        }
        __syncthreads();
    }
}

// ---------------- final concat ----------------
__global__ void final_kernel(float* __restrict__ out) {
    int i = blockIdx.x * blockDim.x + threadIdx.x;
    if (i < BB * 2 * HHD) {
        int b = i >> 10;
        int j = i & 1023;
        out[i] = (j < HHD) ? d_hout[0][b * HHD + j]
                           : d_hout[1][b * HHD + j - HHD];
    }
}

// ---------------- launch ----------------
extern "C" void kernel_launch(void* const* d_in, const int* in_sizes, int n_in,
                              void* d_out, int out_size) {
    const float* x     = (const float*)d_in[0];
    const float* gamma = (const float*)d_in[1];
    const float* beta  = (const float*)d_in[2];
    const float* mean  = (const float*)d_in[3];
    const float* var   = (const float*)d_in[4];
    const float* Wf    = (const float*)d_in[5];
    const float* Uf    = (const float*)d_in[6];
    const float* bf    = (const float*)d_in[7];
    const float* Wb    = (const float*)d_in[8];
    const float* Ub    = (const float*)d_in[9];
    const float* bb    = (const float*)d_in[10];
    float* out = (float*)d_out;

    cudaFuncSetAttribute(lstm_persist, cudaFuncAttributeMaxDynamicSharedMemorySize,
                         LSTM_SMEM);

    bn_prep_kernel<<<1, 512>>>(gamma, beta, mean, var);

    split_x_kernel<<<MR * 256 / 256, 256>>>(x);
    split_w_kernel<<<2 * 256 * G4 / 256, 256>>>(Wf, Wb);

    dim3 ggrid(G4 / 128, MR / 128, 2);
    gemm_tc_kernel<<<ggrid, 256>>>(bf, bb);

    init_kernel<<<64, 256>>>();

    lstm_persist<<<NBLK, 256, LSTM_SMEM>>>(Uf, Ub);

    final_kernel<<<128, 256>>>(out);
}